// round 9
// baseline (speedup 1.0000x reference)
#include <cuda_runtime.h>
#include <cstdint>

// ---------------- Problem constants ----------------
constexpr int NN = 16384;   // nodes per level
constexpr int DD = 256;     // feature dim
constexpr int KP = 16;      // in-degree
constexpr int LL = 16;      // levels

// ---------------- GEMM tiling ----------------
// CTA: 256 threads = 8 warps (2m x 4n), warp tile 64x64, BM=128, BN=256 (full N).
constexpr int BM = 128, BN = 256, BK = 32;
constexpr int STAGES = 4;
constexpr int PAD = 36;                          // floats per SMEM row (conflict-free)
constexpr int A_FLOATS = BM * PAD;               // 4608
constexpr int B_FLOATS = BN * PAD;               // 9216
constexpr int STAGE_BYTES = (A_FLOATS + B_FLOATS) * 4;   // 55296
constexpr int SMEM_BYTES = STAGES * STAGE_BYTES;         // 221184 (<= 227KB opt-in)

// ---------------- Scratch (__device__ globals; alloc-free rule) ----------------
__device__ float g_msg[NN * DD];
__device__ float g_H[NN * DD];
__device__ float g_W1t[DD * DD];   // W1^T, tf32-rna rounded
__device__ float g_W2t[DD * DD];   // W2^T, tf32-rna rounded

// ---------------- Portable PTX helpers (no 'a'-suffix features) ----------------
__device__ __forceinline__ uint32_t smem_u32(const void* p) {
    uint32_t a;
    asm("{ .reg .u64 t; cvta.to.shared.u64 t, %1; cvt.u32.u64 %0, t; }" : "=r"(a) : "l"(p));
    return a;
}
__device__ __forceinline__ void cp16(uint32_t dst, const void* src) {
    asm volatile("cp.async.cg.shared.global [%0], [%1], 16;" :: "r"(dst), "l"(src));
}
#define CP_COMMIT() asm volatile("cp.async.commit_group;" ::: "memory")
#define CP_WAIT(n)  asm volatile("cp.async.wait_group %0;" :: "n"(n) : "memory")

__device__ __forceinline__ void ldsm4(uint32_t& r0, uint32_t& r1, uint32_t& r2, uint32_t& r3,
                                      uint32_t addr) {
    asm volatile("ldmatrix.sync.aligned.m8n8.x4.shared.b16 {%0,%1,%2,%3}, [%4];"
                 : "=r"(r0), "=r"(r1), "=r"(r2), "=r"(r3) : "r"(addr));
}
__device__ __forceinline__ void mma_tf32(float* c, uint32_t a0, uint32_t a1, uint32_t a2,
                                         uint32_t a3, uint32_t b0, uint32_t b1) {
    asm volatile("mma.sync.aligned.m16n8k8.row.col.f32.tf32.tf32.f32 "
                 "{%0,%1,%2,%3}, {%4,%5,%6,%7}, {%8,%9}, {%0,%1,%2,%3};"
                 : "+f"(c[0]), "+f"(c[1]), "+f"(c[2]), "+f"(c[3])
                 : "r"(a0), "r"(a1), "r"(a2), "r"(a3), "r"(b0), "r"(b1));
}

// ---------------- Streaming tf32 GEMM:  C = [relu](A @ Bt^T [+ bias]) ----------------
// A [NN,256] f32 row-major; Bt [256 n][256 k] pre-transposed + tf32-rna rounded.
// Grid = NN/BM = 128 CTAs (one wave, 1 CTA/SM). K in 8 chunks of 32, 4-stage cp.async.
template<bool BIAS_RELU>
__global__ __launch_bounds__(256, 1) void gemm_tf32(
    const float* __restrict__ A, const float* __restrict__ Bt,
    const float* __restrict__ bias, float* __restrict__ C)
{
    extern __shared__ float sm[];
    const uint32_t smb = smem_u32(sm);

    const int tid = threadIdx.x;
    const int lane = tid & 31, wid = tid >> 5;
    const int g = lane >> 2, t = lane & 3;
    const int wm = (wid & 1) * 64;          // 2 m-warps
    const int wn = (wid >> 1) * 64;         // 4 n-warps
    const int bm = blockIdx.x * BM;

    // ---- cp.async base addresses (computed once; loop adds strides) ----
    const int r8 = tid >> 3, v8 = tid & 7;
    const float* Agb = A  + (size_t)(bm + r8) * DD + v8 * 4;
    const float* Bgb = Bt + (size_t)r8 * DD + v8 * 4;
    const uint32_t Asmb = smb + (uint32_t)(r8 * PAD + v8 * 4) * 4u;
    const uint32_t Bsmb = smb + (uint32_t)(A_FLOATS + r8 * PAD + v8 * 4) * 4u;

    auto issue = [&](int kc, int stage) {
        const uint32_t so = (uint32_t)stage * STAGE_BYTES;
        const int go = kc * BK;
        #pragma unroll
        for (int i = 0; i < 4; i++)      // A: 128 rows
            cp16(Asmb + so + (uint32_t)(i * 32 * PAD) * 4u, Agb + go + (size_t)(i * 32) * DD);
        #pragma unroll
        for (int i = 0; i < 8; i++)      // B: 256 rows
            cp16(Bsmb + so + (uint32_t)(i * 32 * PAD) * 4u, Bgb + go + (size_t)(i * 32) * DD);
        CP_COMMIT();
    };

    // ---- ldmatrix base addresses ----
    const int lr = (lane & 7) + ((lane & 16) >> 1);   // 0..15
    const int lc = (lane & 8) >> 1;                   // 0 or 4
    uint32_t a_base[4], b_base[4];
    #pragma unroll
    for (int mf = 0; mf < 4; mf++)
        a_base[mf] = smb + (uint32_t)((wm + mf * 16 + lr) * PAD + lc) * 4u;
    #pragma unroll
    for (int np = 0; np < 4; np++)
        b_base[np] = smb + (uint32_t)(A_FLOATS + (wn + np * 16 + lr) * PAD + lc) * 4u;

    float acc[4][8][4] = {};

    auto compute = [&](int stage) {
        const uint32_t so = (uint32_t)stage * STAGE_BYTES;
        #pragma unroll
        for (int ks = 0; ks < 4; ks++) {
            const uint32_t ko = so + ks * 32u;
            uint32_t a[4][4], b[4][4];
            #pragma unroll
            for (int mf = 0; mf < 4; mf++)
                ldsm4(a[mf][0], a[mf][1], a[mf][2], a[mf][3], a_base[mf] + ko);
            #pragma unroll
            for (int np = 0; np < 4; np++)
                ldsm4(b[np][0], b[np][1], b[np][2], b[np][3], b_base[np] + ko);
            #pragma unroll
            for (int mf = 0; mf < 4; mf++)
                #pragma unroll
                for (int nf = 0; nf < 8; nf++)
                    mma_tf32(acc[mf][nf],
                             a[mf][0], a[mf][2], a[mf][1], a[mf][3],
                             b[nf >> 1][(nf & 1) * 2], b[nf >> 1][(nf & 1) * 2 + 1]);
        }
    };

    // ---- 4-stage pipeline, one barrier per chunk ----
    issue(0, 0); issue(1, 1); issue(2, 2);
    #pragma unroll
    for (int kc = 0; kc < DD / BK; kc++) {
        if (kc <= 5)      { CP_WAIT(2); }
        else if (kc == 6) { CP_WAIT(1); }
        else              { CP_WAIT(0); }
        __syncthreads();
        if (kc + 3 < DD / BK) issue(kc + 3, (kc + 3) & 3);
        compute(kc & 3);
    }

    // ---- epilogue ----
    #pragma unroll
    for (int mf = 0; mf < 4; mf++) {
        const int r0 = bm + wm + mf * 16 + g;
        #pragma unroll
        for (int nf = 0; nf < 8; nf++) {
            const int col = wn + nf * 8 + 2 * t;
            float2 v0, v1;
            if (BIAS_RELU) {
                float2 bb = *(const float2*)(bias + col);
                v0.x = fmaxf(acc[mf][nf][0] + bb.x, 0.f);
                v0.y = fmaxf(acc[mf][nf][1] + bb.y, 0.f);
                v1.x = fmaxf(acc[mf][nf][2] + bb.x, 0.f);
                v1.y = fmaxf(acc[mf][nf][3] + bb.y, 0.f);
            } else {
                v0.x = acc[mf][nf][0]; v0.y = acc[mf][nf][1];
                v1.x = acc[mf][nf][2]; v1.y = acc[mf][nf][3];
            }
            *(float2*)(C + (size_t)r0 * DD + col) = v0;
            *(float2*)(C + (size_t)(r0 + 8) * DD + col) = v1;
        }
    }
}

// ---------------- Gather epilogue:  y = relu(mean_p H[idx_p] + b2) + x ----------------
__global__ __launch_bounds__(256) void gather_epi(
    const float* __restrict__ H, const int* __restrict__ idx,
    const float* __restrict__ b2, const float* __restrict__ x,
    float* __restrict__ y)
{
    const int node = blockIdx.x * 4 + (threadIdx.x >> 6);
    const int c = (threadIdx.x & 63) * 4;
    const int4* ip = (const int4*)(idx + (size_t)node * KP);

    int pr[KP];
    #pragma unroll
    for (int i = 0; i < 4; i++) {
        int4 v = ip[i];
        pr[i*4+0] = v.x; pr[i*4+1] = v.y; pr[i*4+2] = v.z; pr[i*4+3] = v.w;
    }

    float4 s = {0.f, 0.f, 0.f, 0.f};
    #pragma unroll
    for (int p = 0; p < KP; p++) {
        float4 v = *(const float4*)(H + (size_t)pr[p] * DD + c);
        s.x += v.x; s.y += v.y; s.z += v.z; s.w += v.w;
    }
    const float inv = 1.0f / (float)KP;
    float4 bb = *(const float4*)(b2 + c);
    float4 xx = *(const float4*)(x + (size_t)node * DD + c);
    float4 o;
    o.x = fmaxf(s.x * inv + bb.x, 0.f) + xx.x;
    o.y = fmaxf(s.y * inv + bb.y, 0.f) + xx.y;
    o.z = fmaxf(s.z * inv + bb.z, 0.f) + xx.z;
    o.w = fmaxf(s.w * inv + bb.w, 0.f) + xx.w;
    *(float4*)(y + (size_t)node * DD + c) = o;
}

// ------- 256x256 transpose + tf32-rna round (weights -> N-major B operand) -------
__global__ void transpose256(const float* __restrict__ W, float* __restrict__ Wt) {
    __shared__ float tbuf[32][33];
    const int bx = (blockIdx.x & 7) * 32;
    const int by = (blockIdx.x >> 3) * 32;
    const int x = threadIdx.x, y = threadIdx.y;
    #pragma unroll
    for (int i = 0; i < 32; i += 8)
        tbuf[y + i][x] = W[(by + y + i) * DD + bx + x];
    __syncthreads();
    #pragma unroll
    for (int i = 0; i < 32; i += 8) {
        uint32_t r;
        asm("cvt.rna.tf32.f32 %0, %1;" : "=r"(r) : "f"(tbuf[x][y + i]));
        Wt[(bx + y + i) * DD + by + x] = __uint_as_float(r);
    }
}

// ---------------- Launch ----------------
extern "C" void kernel_launch(void* const* d_in, const int* in_sizes, int n_in,
                              void* d_out, int out_size)
{
    const float* x   = (const float*)d_in[0];   // [L, N, D]
    const int*   idx = (const int*)  d_in[1];   // [L-1, N, K]
    const float* W1  = (const float*)d_in[2];   // [D, D]
    const float* b1  = (const float*)d_in[3];   // [D]
    const float* W2  = (const float*)d_in[4];   // [D, D]
    const float* b2  = (const float*)d_in[5];   // [D]
    float* out = (float*)d_out;                 // [L, N, D]

    float *msgp, *Hp, *w1t, *w2t;
    cudaGetSymbolAddress((void**)&msgp, g_msg);
    cudaGetSymbolAddress((void**)&Hp,   g_H);
    cudaGetSymbolAddress((void**)&w1t,  g_W1t);
    cudaGetSymbolAddress((void**)&w2t,  g_W2t);

    cudaFuncSetAttribute(gemm_tf32<true>,  cudaFuncAttributeMaxDynamicSharedMemorySize, SMEM_BYTES);
    cudaFuncSetAttribute(gemm_tf32<false>, cudaFuncAttributeMaxDynamicSharedMemorySize, SMEM_BYTES);

    const size_t lvl = (size_t)NN * DD;

    transpose256<<<64, dim3(32, 8)>>>(W1, w1t);
    transpose256<<<64, dim3(32, 8)>>>(W2, w2t);

    // Level 0: passthrough
    cudaMemcpyAsync(out, x, lvl * sizeof(float), cudaMemcpyDeviceToDevice);

    const int grid = NN / BM;   // 128 CTAs, full N per CTA

    for (int l = 1; l < LL; l++) {
        const float* yprev = out + (size_t)(l - 1) * lvl;
        // msg = relu(yprev @ W1 + b1)
        gemm_tf32<true><<<grid, 256, SMEM_BYTES>>>(yprev, w1t, b1, msgp);
        // H = msg @ W2   (bias/relu deferred; mean commutes with the linear map)
        gemm_tf32<false><<<grid, 256, SMEM_BYTES>>>(msgp, w2t, nullptr, Hp);
        // y = relu(mean_p H[idx_p] + b2) + x[l]
        gather_epi<<<NN / 4, 256>>>(Hp, idx + (size_t)(l - 1) * NN * KP, b2,
                                    x + (size_t)l * lvl, out + (size_t)l * lvl);
    }
}

// round 11
// speedup vs baseline: 1.8793x; 1.8793x over previous
#include <cuda_runtime.h>
#include <cstdint>

// ---------------- Problem constants ----------------
constexpr int NN = 16384;   // nodes per level
constexpr int DD = 256;     // feature dim
constexpr int KP = 16;      // in-degree
constexpr int LL = 16;      // levels

// ---------------- Fused-level GEMM tiling ----------------
// CTA: 512 threads = 16 warps (4m x 4n), warp tile 32x64. BM=128, BN=256 (full), BK=32.
constexpr int THREADS = 512;
constexpr int BM = 128, BN = 256, BK = 32;
constexpr int NCH = DD / BK;                    // 8 K-chunks
constexpr int PAD = 36;                         // floats per SMEM row (conflict-free, 16B-mult)
constexpr int ACH = BM * PAD;                   // 4608 floats: one A/MSG chunk buffer
constexpr int BCH = BN * PAD;                   // 9216 floats: one B stage
constexpr int MSG_FLOATS = NCH * ACH;           // 36864 floats (147456 B): 8 chunk buffers
constexpr int BOFF = MSG_FLOATS;                // B region offset (floats)
constexpr int SMEM_FLOATS = MSG_FLOATS + 2 * BCH;   // 55296
constexpr int SMEM_BYTES = SMEM_FLOATS * 4;         // 221184 B (<= 227KB opt-in)

// ---------------- Scratch (__device__ globals; alloc-free rule) ----------------
__device__ float g_H[NN * DD];
__device__ float g_W1t[DD * DD];   // W1^T, tf32-rna rounded
__device__ float g_W2t[DD * DD];   // W2^T, tf32-rna rounded

// ---------------- Portable PTX helpers (no 'a'-suffix features) ----------------
__device__ __forceinline__ uint32_t smem_u32(const void* p) {
    uint32_t a;
    asm("{ .reg .u64 t; cvta.to.shared.u64 t, %1; cvt.u32.u64 %0, t; }" : "=r"(a) : "l"(p));
    return a;
}
__device__ __forceinline__ void cp16(uint32_t dst, const void* src) {
    asm volatile("cp.async.cg.shared.global [%0], [%1], 16;" :: "r"(dst), "l"(src));
}
#define CP_COMMIT() asm volatile("cp.async.commit_group;" ::: "memory")
#define CP_WAIT(n)  asm volatile("cp.async.wait_group %0;" :: "n"(n) : "memory")

__device__ __forceinline__ void ldsm4(uint32_t& r0, uint32_t& r1, uint32_t& r2, uint32_t& r3,
                                      uint32_t addr) {
    asm volatile("ldmatrix.sync.aligned.m8n8.x4.shared.b16 {%0,%1,%2,%3}, [%4];"
                 : "=r"(r0), "=r"(r1), "=r"(r2), "=r"(r3) : "r"(addr));
}
__device__ __forceinline__ void mma_tf32(float* c, uint32_t a0, uint32_t a1, uint32_t a2,
                                         uint32_t a3, uint32_t b0, uint32_t b1) {
    asm volatile("mma.sync.aligned.m16n8k8.row.col.f32.tf32.tf32.f32 "
                 "{%0,%1,%2,%3}, {%4,%5,%6,%7}, {%8,%9}, {%0,%1,%2,%3};"
                 : "+f"(c[0]), "+f"(c[1]), "+f"(c[2]), "+f"(c[3])
                 : "r"(a0), "r"(a1), "r"(a2), "r"(a3), "r"(b0), "r"(b1));
}

// ================= Fused level kernel =================
//   MSG = relu(A @ W1t^T + b1)   (kept in SMEM, operand layout)
//   H   = MSG @ W2t^T            (written to GMEM; bias/relu deferred to gather)
// A [NN,256] f32 row-major; W1t/W2t [256 n][256 k] pre-transposed, tf32-rna rounded.
__global__ __launch_bounds__(THREADS, 1) void fused_level(
    const float* __restrict__ A, const float* __restrict__ W1t,
    const float* __restrict__ b1, const float* __restrict__ W2t,
    float* __restrict__ H)
{
    extern __shared__ float sm[];
    const uint32_t smb = smem_u32(sm);

    const int tid = threadIdx.x;
    const int lane = tid & 31, wid = tid >> 5;
    const int g = lane >> 2, t = lane & 3;
    const int wm = (wid & 3) * 32;           // 4 m-warps
    const int wn = (wid >> 2) * 64;          // 4 n-warps
    const int bm = blockIdx.x * BM;

    // ---- cp.async mappings (512 threads) ----
    // A: 128 rows x 8 float4 = 1024 xfers -> 2/thread (rows ar0, ar0+64)
    // B: 256 rows x 8 float4 = 2048 xfers -> 4/thread (rows ar0 + i*64, i<4)
    const int ar0 = tid >> 3, av0 = tid & 7;            // ar0 in [0,64)
    const float* Agb = A + (size_t)(bm + ar0) * DD + av0 * 4;
    const uint32_t Asm0 = (uint32_t)(ar0 * PAD + av0 * 4) * 4u;

    auto issueA = [&](int kc) {                         // -> MSG chunk buffer kc
        const uint32_t dst = smb + (uint32_t)(kc * ACH) * 4u + Asm0;
        const int go = kc * BK;
        cp16(dst, Agb + go);
        cp16(dst + (uint32_t)(64 * PAD) * 4u, Agb + go + (size_t)64 * DD);
    };
    auto issueB = [&](const float* W, int kc, int stage) {
        const uint32_t dst = smb + (uint32_t)(BOFF + stage * BCH + ar0 * PAD + av0 * 4) * 4u;
        const float* src = W + (size_t)ar0 * DD + kc * BK + av0 * 4;
        #pragma unroll
        for (int i = 0; i < 4; i++)                     // rows ar0 + i*64 : covers 0..255
            cp16(dst + (uint32_t)(i * 64 * PAD) * 4u, src + (size_t)(i * 64) * DD);
    };

    // ---- ldmatrix lane mapping ----
    const int lr = (lane & 7) + ((lane & 16) >> 1);     // 0..15
    const int lc = (lane & 8) >> 1;                     // 0 or 4
    uint32_t a_off[2], b_off[4];
    #pragma unroll
    for (int mf = 0; mf < 2; mf++)
        a_off[mf] = (uint32_t)((wm + mf * 16 + lr) * PAD + lc) * 4u;
    #pragma unroll
    for (int np = 0; np < 4; np++)
        b_off[np] = (uint32_t)(BOFF + (wn + np * 16 + lr) * PAD + lc) * 4u;

    float acc[2][8][4] = {};

    auto compute = [&](int kc, int stage) {
        const uint32_t abase = smb + (uint32_t)(kc * ACH) * 4u;
        const uint32_t bbase = smb + (uint32_t)(stage * BCH) * 4u;
        #pragma unroll
        for (int ks = 0; ks < 4; ks++) {
            const uint32_t ko = ks * 32u;
            uint32_t a[2][4], b[4][4];
            #pragma unroll
            for (int mf = 0; mf < 2; mf++)
                ldsm4(a[mf][0], a[mf][1], a[mf][2], a[mf][3], abase + a_off[mf] + ko);
            #pragma unroll
            for (int np = 0; np < 4; np++)
                ldsm4(b[np][0], b[np][1], b[np][2], b[np][3], bbase + b_off[np] + ko);
            #pragma unroll
            for (int mf = 0; mf < 2; mf++)
                #pragma unroll
                for (int nf = 0; nf < 8; nf++)
                    mma_tf32(acc[mf][nf],
                             a[mf][0], a[mf][2], a[mf][1], a[mf][3],
                             b[nf >> 1][(nf & 1) * 2], b[nf >> 1][(nf & 1) * 2 + 1]);
        }
    };

    // ================= Phase 1: MSG = relu(A @ W1 + b1) =================
    // A chunks stream into the 8 MSG buffers (no recycling -> no WAR on A).
    // W1 double-buffered in the 2 B stages.
    issueA(0); issueB(W1t, 0, 0); CP_COMMIT();
    issueA(1); issueB(W1t, 1, 1); CP_COMMIT();
    #pragma unroll
    for (int kc = 0; kc < NCH; kc++) {
        if (kc < NCH - 1) { CP_WAIT(1); } else { CP_WAIT(0); }
        __syncthreads();
        compute(kc, kc & 1);
        __syncthreads();
        if (kc + 2 < NCH) { issueA(kc + 2); issueB(W1t, kc + 2, kc & 1); CP_COMMIT(); }
    }

    // Prefetch W2 chunks 0,1 (B stages are free; MSG region untouched by these)
    issueB(W2t, 0, 0); CP_COMMIT();
    issueB(W2t, 1, 1); CP_COMMIT();

    // Phase-1 epilogue: relu(acc + b1) -> MSG buffers (A-operand layout), overwrite staged A.
    #pragma unroll
    for (int mf = 0; mf < 2; mf++) {
        const int r0 = wm + mf * 16 + g;
        #pragma unroll
        for (int nf = 0; nf < 8; nf++) {
            const int col = wn + nf * 8 + 2 * t;
            const int ch = col >> 5, kcol = col & 31;
            float2 bb = *(const float2*)(b1 + col);
            float2 v0, v1;
            v0.x = fmaxf(acc[mf][nf][0] + bb.x, 0.f);
            v0.y = fmaxf(acc[mf][nf][1] + bb.y, 0.f);
            v1.x = fmaxf(acc[mf][nf][2] + bb.x, 0.f);
            v1.y = fmaxf(acc[mf][nf][3] + bb.y, 0.f);
            *(float2*)(sm + ch * ACH + r0 * PAD + kcol) = v0;
            *(float2*)(sm + ch * ACH + (r0 + 8) * PAD + kcol) = v1;
            acc[mf][nf][0] = 0.f; acc[mf][nf][1] = 0.f;
            acc[mf][nf][2] = 0.f; acc[mf][nf][3] = 0.f;
        }
    }

    // ================= Phase 2: H = MSG @ W2 =================
    #pragma unroll
    for (int kc = 0; kc < NCH; kc++) {
        if (kc < NCH - 1) { CP_WAIT(1); } else { CP_WAIT(0); }
        __syncthreads();            // publishes MSG writes (kc==0) + B stage ready
        compute(kc, kc & 1);
        __syncthreads();
        if (kc + 2 < NCH) { issueB(W2t, kc + 2, kc & 1); CP_COMMIT(); }
    }

    // Phase-2 epilogue: raw H to GMEM
    #pragma unroll
    for (int mf = 0; mf < 2; mf++) {
        const int r0 = bm + wm + mf * 16 + g;
        #pragma unroll
        for (int nf = 0; nf < 8; nf++) {
            const int col = wn + nf * 8 + 2 * t;
            float2 v0, v1;
            v0.x = acc[mf][nf][0]; v0.y = acc[mf][nf][1];
            v1.x = acc[mf][nf][2]; v1.y = acc[mf][nf][3];
            *(float2*)(H + (size_t)r0 * DD + col) = v0;
            *(float2*)(H + (size_t)(r0 + 8) * DD + col) = v1;
        }
    }
}

// ---------------- Gather epilogue:  y = relu(mean_p H[idx_p] + b2) + x ----------------
__global__ __launch_bounds__(256) void gather_epi(
    const float* __restrict__ H, const int* __restrict__ idx,
    const float* __restrict__ b2, const float* __restrict__ x,
    float* __restrict__ y)
{
    const int node = blockIdx.x * 4 + (threadIdx.x >> 6);
    const int c = (threadIdx.x & 63) * 4;
    const int4* ip = (const int4*)(idx + (size_t)node * KP);

    int pr[KP];
    #pragma unroll
    for (int i = 0; i < 4; i++) {
        int4 v = ip[i];
        pr[i*4+0] = v.x; pr[i*4+1] = v.y; pr[i*4+2] = v.z; pr[i*4+3] = v.w;
    }

    float4 s = {0.f, 0.f, 0.f, 0.f};
    #pragma unroll
    for (int p = 0; p < KP; p++) {
        float4 v = *(const float4*)(H + (size_t)pr[p] * DD + c);
        s.x += v.x; s.y += v.y; s.z += v.z; s.w += v.w;
    }
    const float inv = 1.0f / (float)KP;
    float4 bb = *(const float4*)(b2 + c);
    float4 xx = *(const float4*)(x + (size_t)node * DD + c);
    float4 o;
    o.x = fmaxf(s.x * inv + bb.x, 0.f) + xx.x;
    o.y = fmaxf(s.y * inv + bb.y, 0.f) + xx.y;
    o.z = fmaxf(s.z * inv + bb.z, 0.f) + xx.z;
    o.w = fmaxf(s.w * inv + bb.w, 0.f) + xx.w;
    *(float4*)(y + (size_t)node * DD + c) = o;
}

// ------- 256x256 transpose + tf32-rna round (weights -> N-major B operand) -------
__global__ void transpose256(const float* __restrict__ W, float* __restrict__ Wt) {
    __shared__ float tbuf[32][33];
    const int bx = (blockIdx.x & 7) * 32;
    const int by = (blockIdx.x >> 3) * 32;
    const int x = threadIdx.x, y = threadIdx.y;
    #pragma unroll
    for (int i = 0; i < 32; i += 8)
        tbuf[y + i][x] = W[(by + y + i) * DD + bx + x];
    __syncthreads();
    #pragma unroll
    for (int i = 0; i < 32; i += 8) {
        uint32_t r;
        asm("cvt.rna.tf32.f32 %0, %1;" : "=r"(r) : "f"(tbuf[x][y + i]));
        Wt[(bx + y + i) * DD + by + x] = __uint_as_float(r);
    }
}

// ---------------- Launch ----------------
extern "C" void kernel_launch(void* const* d_in, const int* in_sizes, int n_in,
                              void* d_out, int out_size)
{
    const float* x   = (const float*)d_in[0];   // [L, N, D]
    const int*   idx = (const int*)  d_in[1];   // [L-1, N, K]
    const float* W1  = (const float*)d_in[2];   // [D, D]
    const float* b1  = (const float*)d_in[3];   // [D]
    const float* W2  = (const float*)d_in[4];   // [D, D]
    const float* b2  = (const float*)d_in[5];   // [D]
    float* out = (float*)d_out;                 // [L, N, D]

    float *Hp, *w1t, *w2t;
    cudaGetSymbolAddress((void**)&Hp,  g_H);
    cudaGetSymbolAddress((void**)&w1t, g_W1t);
    cudaGetSymbolAddress((void**)&w2t, g_W2t);

    cudaFuncSetAttribute(fused_level, cudaFuncAttributeMaxDynamicSharedMemorySize, SMEM_BYTES);

    const size_t lvl = (size_t)NN * DD;

    transpose256<<<64, dim3(32, 8)>>>(W1, w1t);
    transpose256<<<64, dim3(32, 8)>>>(W2, w2t);

    // Level 0: passthrough
    cudaMemcpyAsync(out, x, lvl * sizeof(float), cudaMemcpyDeviceToDevice);

    const int grid = NN / BM;   // 128 CTAs, one wave

    for (int l = 1; l < LL; l++) {
        const float* yprev = out + (size_t)(l - 1) * lvl;
        // H = relu(yprev @ W1 + b1) @ W2   (msg stays in SMEM)
        fused_level<<<grid, THREADS, SMEM_BYTES>>>(yprev, w1t, b1, w2t, Hp);
        // y = relu(mean_p H[idx_p] + b2) + x[l]
        gather_epi<<<NN / 4, 256>>>(Hp, idx + (size_t)(l - 1) * NN * KP, b2,
                                    x + (size_t)l * lvl, out + (size_t)l * lvl);
    }
}

// round 12
// speedup vs baseline: 3.1094x; 1.6545x over previous
#include <cuda_runtime.h>
#include <cuda_fp16.h>
#include <cstdint>

// ---------------- Problem constants ----------------
constexpr int NN = 16384;   // nodes per level
constexpr int DD = 256;     // feature dim
constexpr int KP = 16;      // in-degree
constexpr int LL = 16;      // levels

// ---------------- Fused-level GEMM tiling (fp16 operands, fp32 accum) ----------------
// CTA: 512 threads = 16 warps (4m x 4n), warp tile 32x64. BM=128, BN=256 (full), BK=64.
constexpr int THREADS = 512;
constexpr int BM = 128, BN = 256, BK = 64;
constexpr int NCH = DD / BK;                    // 4 K-chunks
constexpr int PADH = 72;                        // halves per SMEM row (144B, conflict-free)
constexpr int ACH = BM * PADH;                  // 9216 halves : one A/MSG chunk buffer
constexpr int BCH = BN * PADH;                  // 18432 halves: one B stage
constexpr int MSGH = NCH * ACH;                 // 36864 halves (73728 B): 4 chunk buffers
constexpr int BOFF = MSGH;                      // B region offset (halves)
constexpr int SMEM_BYTES = (MSGH + 2 * BCH) * 2;    // 147456 B

// ---------------- Scratch (__device__ globals; alloc-free rule) ----------------
__device__ __half g_Hh[NN * DD];    // H (pre-gather), fp16
__device__ __half g_yh[NN * DD];    // fp16 copy of current level's y (A operand)
__device__ __half g_W1h[DD * DD];   // W1^T, fp16 rna
__device__ __half g_W2h[DD * DD];   // W2^T, fp16 rna

// ---------------- Portable PTX helpers ----------------
__device__ __forceinline__ uint32_t smem_u32(const void* p) {
    uint32_t a;
    asm("{ .reg .u64 t; cvta.to.shared.u64 t, %1; cvt.u32.u64 %0, t; }" : "=r"(a) : "l"(p));
    return a;
}
__device__ __forceinline__ void cp16(uint32_t dst, const void* src) {
    asm volatile("cp.async.cg.shared.global [%0], [%1], 16;" :: "r"(dst), "l"(src));
}
#define CP_COMMIT() asm volatile("cp.async.commit_group;" ::: "memory")
#define CP_WAIT(n)  asm volatile("cp.async.wait_group %0;" :: "n"(n) : "memory")

__device__ __forceinline__ void ldsm4(uint32_t& r0, uint32_t& r1, uint32_t& r2, uint32_t& r3,
                                      uint32_t addr) {
    asm volatile("ldmatrix.sync.aligned.m8n8.x4.shared.b16 {%0,%1,%2,%3}, [%4];"
                 : "=r"(r0), "=r"(r1), "=r"(r2), "=r"(r3) : "r"(addr));
}
__device__ __forceinline__ void mma_f16(float* c, uint32_t a0, uint32_t a1, uint32_t a2,
                                        uint32_t a3, uint32_t b0, uint32_t b1) {
    asm volatile("mma.sync.aligned.m16n8k16.row.col.f32.f16.f16.f32 "
                 "{%0,%1,%2,%3}, {%4,%5,%6,%7}, {%8,%9}, {%0,%1,%2,%3};"
                 : "+f"(c[0]), "+f"(c[1]), "+f"(c[2]), "+f"(c[3])
                 : "r"(a0), "r"(a1), "r"(a2), "r"(a3), "r"(b0), "r"(b1));
}

// ================= Fused level kernel (fp16) =================
//   MSG = relu(A @ W1h^T + b1)  (fp16, kept in SMEM operand layout)
//   H   = MSG @ W2h^T           (fp16 to GMEM; bias/relu/mean deferred to gather)
__global__ __launch_bounds__(THREADS, 1) void fused_level(
    const __half* __restrict__ A, const __half* __restrict__ W1h,
    const float* __restrict__ b1, const __half* __restrict__ W2h,
    __half* __restrict__ H)
{
    extern __shared__ __half smh[];
    const uint32_t smb = smem_u32(smh);

    const int tid = threadIdx.x;
    const int lane = tid & 31, wid = tid >> 5;
    const int g = lane >> 2, t = lane & 3;
    const int wm = (wid & 3) * 32;           // 4 m-warps
    const int wn = (wid >> 2) * 64;          // 4 n-warps
    const int bm = blockIdx.x * BM;

    // ---- cp.async mappings: chunk row = 64 halves = 128B = 8 x 16B ----
    const int ar0 = tid >> 3, av0 = tid & 7;            // ar0 in [0,64)
    const __half* Agb = A + (size_t)(bm + ar0) * DD + av0 * 8;
    const uint32_t Asm0 = (uint32_t)(ar0 * PADH + av0 * 8) * 2u;

    auto issueA = [&](int kc) {                         // -> MSG chunk buffer kc
        const uint32_t dst = smb + (uint32_t)(kc * ACH) * 2u + Asm0;
        const int go = kc * BK;
        cp16(dst, Agb + go);
        cp16(dst + (uint32_t)(64 * PADH) * 2u, Agb + go + (size_t)64 * DD);
    };
    auto issueB = [&](const __half* W, int kc, int stage) {
        const uint32_t dst = smb + (uint32_t)(BOFF + stage * BCH + ar0 * PADH + av0 * 8) * 2u;
        const __half* src = W + (size_t)ar0 * DD + kc * BK + av0 * 8;
        #pragma unroll
        for (int i = 0; i < 4; i++)                     // rows ar0 + i*64 : covers 0..255
            cp16(dst + (uint32_t)(i * 64 * PADH) * 2u, src + (size_t)(i * 64) * DD);
    };

    // ---- ldmatrix lane mappings ----
    const int arow = lane & 15;                 // A tiles: m = arow, colhalves = (lane>>4)*8
    const int acol = (lane >> 4) * 8;
    const int brow = (lane & 7) + ((lane >> 4) << 3);   // B tiles: n-row, colhalves toggle
    const int bcol = ((lane >> 3) & 1) * 8;
    uint32_t a_off[2], b_off[4];
    #pragma unroll
    for (int mf = 0; mf < 2; mf++)
        a_off[mf] = (uint32_t)((wm + mf * 16 + arow) * PADH + acol) * 2u;
    #pragma unroll
    for (int np = 0; np < 4; np++)
        b_off[np] = (uint32_t)(BOFF + (wn + np * 16 + brow) * PADH + bcol) * 2u;

    float acc[2][8][4] = {};

    auto compute = [&](int kc, int stage) {
        const uint32_t abase = smb + (uint32_t)(kc * ACH) * 2u;
        const uint32_t bbase = smb + (uint32_t)(stage * BCH) * 2u;
        #pragma unroll
        for (int ks = 0; ks < 4; ks++) {                // 4 x k16 = BK 64
            const uint32_t ko = ks * 32u;               // 16 halves = 32 B
            uint32_t a[2][4], b[4][4];
            #pragma unroll
            for (int mf = 0; mf < 2; mf++)
                ldsm4(a[mf][0], a[mf][1], a[mf][2], a[mf][3], abase + a_off[mf] + ko);
            #pragma unroll
            for (int np = 0; np < 4; np++)
                ldsm4(b[np][0], b[np][1], b[np][2], b[np][3], bbase + b_off[np] + ko);
            #pragma unroll
            for (int mf = 0; mf < 2; mf++)
                #pragma unroll
                for (int nf = 0; nf < 8; nf++)
                    mma_f16(acc[mf][nf],
                            a[mf][0], a[mf][1], a[mf][2], a[mf][3],
                            b[nf >> 1][(nf & 1) * 2], b[nf >> 1][(nf & 1) * 2 + 1]);
        }
    };

    // ================= Phase 1: MSG = relu(A @ W1 + b1) =================
    issueA(0); issueB(W1h, 0, 0); CP_COMMIT();
    issueA(1); issueB(W1h, 1, 1); CP_COMMIT();
    #pragma unroll
    for (int kc = 0; kc < NCH; kc++) {
        if (kc < NCH - 1) { CP_WAIT(1); } else { CP_WAIT(0); }
        __syncthreads();
        compute(kc, kc & 1);
        __syncthreads();
        if (kc + 2 < NCH) { issueA(kc + 2); issueB(W1h, kc + 2, kc & 1); CP_COMMIT(); }
    }

    // Prefetch W2 chunks 0,1
    issueB(W2h, 0, 0); CP_COMMIT();
    issueB(W2h, 1, 1); CP_COMMIT();

    // Phase-1 epilogue: relu(acc + b1) -> MSG buffers as fp16 (A-operand layout)
    #pragma unroll
    for (int mf = 0; mf < 2; mf++) {
        const int r0 = wm + mf * 16 + g;
        #pragma unroll
        for (int nf = 0; nf < 8; nf++) {
            const int col = wn + nf * 8 + 2 * t;        // n index 0..255 (even)
            const int ch = col >> 6, kcol = col & 63;   // chunk + within-chunk k
            float2 bb = *(const float2*)(b1 + col);
            float2 v0, v1;
            v0.x = fmaxf(acc[mf][nf][0] + bb.x, 0.f);
            v0.y = fmaxf(acc[mf][nf][1] + bb.y, 0.f);
            v1.x = fmaxf(acc[mf][nf][2] + bb.x, 0.f);
            v1.y = fmaxf(acc[mf][nf][3] + bb.y, 0.f);
            *(__half2*)(smh + ch * ACH + r0 * PADH + kcol) = __float22half2_rn(v0);
            *(__half2*)(smh + ch * ACH + (r0 + 8) * PADH + kcol) = __float22half2_rn(v1);
            acc[mf][nf][0] = 0.f; acc[mf][nf][1] = 0.f;
            acc[mf][nf][2] = 0.f; acc[mf][nf][3] = 0.f;
        }
    }

    // ================= Phase 2: H = MSG @ W2 =================
    #pragma unroll
    for (int kc = 0; kc < NCH; kc++) {
        if (kc < NCH - 1) { CP_WAIT(1); } else { CP_WAIT(0); }
        __syncthreads();            // publishes MSG writes (kc==0) + B stage ready
        compute(kc, kc & 1);
        __syncthreads();
        if (kc + 2 < NCH) { issueB(W2h, kc + 2, kc & 1); CP_COMMIT(); }
    }

    // Phase-2 epilogue: H (raw) to GMEM as fp16
    #pragma unroll
    for (int mf = 0; mf < 2; mf++) {
        const int r0 = bm + wm + mf * 16 + g;
        #pragma unroll
        for (int nf = 0; nf < 8; nf++) {
            const int col = wn + nf * 8 + 2 * t;
            float2 v0, v1;
            v0.x = acc[mf][nf][0]; v0.y = acc[mf][nf][1];
            v1.x = acc[mf][nf][2]; v1.y = acc[mf][nf][3];
            *(__half2*)(H + (size_t)r0 * DD + col) = __float22half2_rn(v0);
            *(__half2*)(H + (size_t)(r0 + 8) * DD + col) = __float22half2_rn(v1);
        }
    }
}

// ------- Gather epilogue: y = relu(mean_p H[idx_p] + b2) + x ; also writes yh = fp16(y) -------
// Block 256 = 8 nodes x 32 threads; each thread owns 8 columns (16B of fp16).
__global__ __launch_bounds__(256) void gather_epi(
    const __half* __restrict__ H, const int* __restrict__ idx,
    const float* __restrict__ b2, const float* __restrict__ x,
    float* __restrict__ y, __half* __restrict__ yh)
{
    const int node = blockIdx.x * 8 + (threadIdx.x >> 5);
    const int co = (threadIdx.x & 31) * 8;
    const int4* ip = (const int4*)(idx + (size_t)node * KP);

    int pr[KP];
    #pragma unroll
    for (int i = 0; i < 4; i++) {
        int4 v = ip[i];
        pr[i*4+0] = v.x; pr[i*4+1] = v.y; pr[i*4+2] = v.z; pr[i*4+3] = v.w;
    }

    float s[8] = {};
    #pragma unroll
    for (int p = 0; p < KP; p++) {
        uint4 u = *(const uint4*)(H + (size_t)pr[p] * DD + co);
        const __half2* hp = (const __half2*)&u;
        #pragma unroll
        for (int j = 0; j < 4; j++) {
            float2 f = __half22float2(hp[j]);
            s[j*2]   += f.x;
            s[j*2+1] += f.y;
        }
    }

    const float inv = 1.0f / (float)KP;
    float4 bb0 = *(const float4*)(b2 + co);
    float4 bb1 = *(const float4*)(b2 + co + 4);
    float4 xx0 = *(const float4*)(x + (size_t)node * DD + co);
    float4 xx1 = *(const float4*)(x + (size_t)node * DD + co + 4);
    float o[8];
    o[0] = fmaxf(s[0]*inv + bb0.x, 0.f) + xx0.x;
    o[1] = fmaxf(s[1]*inv + bb0.y, 0.f) + xx0.y;
    o[2] = fmaxf(s[2]*inv + bb0.z, 0.f) + xx0.z;
    o[3] = fmaxf(s[3]*inv + bb0.w, 0.f) + xx0.w;
    o[4] = fmaxf(s[4]*inv + bb1.x, 0.f) + xx1.x;
    o[5] = fmaxf(s[5]*inv + bb1.y, 0.f) + xx1.y;
    o[6] = fmaxf(s[6]*inv + bb1.z, 0.f) + xx1.z;
    o[7] = fmaxf(s[7]*inv + bb1.w, 0.f) + xx1.w;

    float4* yo = (float4*)(y + (size_t)node * DD + co);
    yo[0] = make_float4(o[0], o[1], o[2], o[3]);
    yo[1] = make_float4(o[4], o[5], o[6], o[7]);

    uint4 hv;
    __half2* hq = (__half2*)&hv;
    hq[0] = __float22half2_rn(make_float2(o[0], o[1]));
    hq[1] = __float22half2_rn(make_float2(o[2], o[3]));
    hq[2] = __float22half2_rn(make_float2(o[4], o[5]));
    hq[3] = __float22half2_rn(make_float2(o[6], o[7]));
    *(uint4*)(yh + (size_t)node * DD + co) = hv;
}

// ------- 256x256 transpose + fp16 rna (weights -> N-major fp16 B operand) -------
__global__ void transpose256h(const float* __restrict__ W, __half* __restrict__ Wt) {
    __shared__ float tbuf[32][33];
    const int bx = (blockIdx.x & 7) * 32;
    const int by = (blockIdx.x >> 3) * 32;
    const int x = threadIdx.x, y = threadIdx.y;
    #pragma unroll
    for (int i = 0; i < 32; i += 8)
        tbuf[y + i][x] = W[(by + y + i) * DD + bx + x];
    __syncthreads();
    #pragma unroll
    for (int i = 0; i < 32; i += 8)
        Wt[(bx + y + i) * DD + by + x] = __float2half_rn(tbuf[x][y + i]);
}

// ------- f32 -> f16 bulk convert (level-0 A operand init) -------
__global__ __launch_bounds__(256) void f32tof16(const float* __restrict__ in,
                                                __half* __restrict__ out) {
    const size_t i = ((size_t)blockIdx.x * 256 + threadIdx.x) * 8;
    float4 v0 = *(const float4*)(in + i);
    float4 v1 = *(const float4*)(in + i + 4);
    uint4 hv;
    __half2* hq = (__half2*)&hv;
    hq[0] = __float22half2_rn(make_float2(v0.x, v0.y));
    hq[1] = __float22half2_rn(make_float2(v0.z, v0.w));
    hq[2] = __float22half2_rn(make_float2(v1.x, v1.y));
    hq[3] = __float22half2_rn(make_float2(v1.z, v1.w));
    *(uint4*)(out + i) = hv;
}

// ---------------- Launch ----------------
extern "C" void kernel_launch(void* const* d_in, const int* in_sizes, int n_in,
                              void* d_out, int out_size)
{
    const float* x   = (const float*)d_in[0];   // [L, N, D]
    const int*   idx = (const int*)  d_in[1];   // [L-1, N, K]
    const float* W1  = (const float*)d_in[2];   // [D, D]
    const float* b1  = (const float*)d_in[3];   // [D]
    const float* W2  = (const float*)d_in[4];   // [D, D]
    const float* b2  = (const float*)d_in[5];   // [D]
    float* out = (float*)d_out;                 // [L, N, D]

    __half *Hh, *yh, *w1h, *w2h;
    cudaGetSymbolAddress((void**)&Hh,  g_Hh);
    cudaGetSymbolAddress((void**)&yh,  g_yh);
    cudaGetSymbolAddress((void**)&w1h, g_W1h);
    cudaGetSymbolAddress((void**)&w2h, g_W2h);

    cudaFuncSetAttribute(fused_level, cudaFuncAttributeMaxDynamicSharedMemorySize, SMEM_BYTES);

    const size_t lvl = (size_t)NN * DD;

    transpose256h<<<64, dim3(32, 8)>>>(W1, w1h);
    transpose256h<<<64, dim3(32, 8)>>>(W2, w2h);

    // Level 0: fp32 passthrough + fp16 operand copy
    cudaMemcpyAsync(out, x, lvl * sizeof(float), cudaMemcpyDeviceToDevice);
    f32tof16<<<NN * DD / (256 * 8), 256>>>(x, yh);

    const int grid = NN / BM;   // 128 CTAs, one wave

    for (int l = 1; l < LL; l++) {
        // H = relu(yh @ W1 + b1) @ W2   (msg stays in SMEM; all fp16 operands)
        fused_level<<<grid, THREADS, SMEM_BYTES>>>(yh, w1h, b1, w2h, Hh);
        // y = relu(mean_p H[idx_p] + b2) + x[l]  ; yh = fp16(y) for next level
        gather_epi<<<NN / 8, 256>>>(Hh, idx + (size_t)(l - 1) * NN * KP, b2,
                                    x + (size_t)l * lvl, out + (size_t)l * lvl, yh);
    }
}

// round 13
// speedup vs baseline: 3.3554x; 1.0791x over previous
#include <cuda_runtime.h>
#include <cuda_fp16.h>
#include <cstdint>

// ---------------- Problem constants ----------------
constexpr int NN = 16384;   // nodes per level
constexpr int DD = 256;     // feature dim
constexpr int KP = 16;      // in-degree
constexpr int LL = 16;      // levels

// ---------------- Fused-level tiling (fp16 operands, fp32 accum) ----------------
// CTA: 512 threads = 16 warps (4m x 4n), warp tile 32x64. BM=128, BN=256, BK=64.
constexpr int THREADS = 512;
constexpr int BM = 128, BN = 256, BK = 64;
constexpr int NCH = DD / BK;                    // 4 K-chunks per GEMM
constexpr int PADH = 72;                        // halves per SMEM row (144B, conflict-free)
constexpr int ACH = BM * PADH;                  // 9216 halves : one A/MSG chunk buffer
constexpr int BCH = BN * PADH;                  // 18432 halves: one B stage
constexpr int MSGH = NCH * ACH;                 // 36864 halves : 4 A chunk buffers
constexpr int BOFF = MSGH;                      // B region offset (halves)
constexpr int BSTAGES = 3;
constexpr int SMEM_BYTES = (MSGH + BSTAGES * BCH) * 2;   // 184320 B

// ---------------- Scratch (__device__ globals; alloc-free rule) ----------------
__device__ __half g_Ha[NN * DD];    // H double buffer A
__device__ __half g_Hb[NN * DD];    // H double buffer B
__device__ __half g_W1h[DD * DD];   // W1^T, fp16 rna
__device__ __half g_W2h[DD * DD];   // W2^T, fp16 rna

// ---------------- Portable PTX helpers ----------------
__device__ __forceinline__ uint32_t smem_u32(const void* p) {
    uint32_t a;
    asm("{ .reg .u64 t; cvta.to.shared.u64 t, %1; cvt.u32.u64 %0, t; }" : "=r"(a) : "l"(p));
    return a;
}
__device__ __forceinline__ void cp16(uint32_t dst, const void* src) {
    asm volatile("cp.async.cg.shared.global [%0], [%1], 16;" :: "r"(dst), "l"(src));
}
#define CP_COMMIT() asm volatile("cp.async.commit_group;" ::: "memory")
#define CP_WAIT(n)  asm volatile("cp.async.wait_group %0;" :: "n"(n) : "memory")

__device__ __forceinline__ void ldsm4(uint32_t& r0, uint32_t& r1, uint32_t& r2, uint32_t& r3,
                                      uint32_t addr) {
    asm volatile("ldmatrix.sync.aligned.m8n8.x4.shared.b16 {%0,%1,%2,%3}, [%4];"
                 : "=r"(r0), "=r"(r1), "=r"(r2), "=r"(r3) : "r"(addr));
}
__device__ __forceinline__ void mma_f16(float* c, uint32_t a0, uint32_t a1, uint32_t a2,
                                        uint32_t a3, uint32_t b0, uint32_t b1) {
    asm volatile("mma.sync.aligned.m16n8k16.row.col.f32.f16.f16.f32 "
                 "{%0,%1,%2,%3}, {%4,%5,%6,%7}, {%8,%9}, {%0,%1,%2,%3};"
                 : "+f"(c[0]), "+f"(c[1]), "+f"(c[2]), "+f"(c[3])
                 : "r"(a0), "r"(a1), "r"(a2), "r"(a3), "r"(b0), "r"(b1));
}

// ================= Fused level kernel =================
// MODE 0:  A = fp16(x0 rows)                       (level 1: no gather)
// MODE 1:  A = fp16(relu(mean_p Hprev[idx_p]+b2)+xl), fp32 A also written to yout
// Then:    MSG = relu(A @ W1h^T + b1)   (SMEM only)
//          Hout = MSG @ W2h^T           (fp16 GMEM)
template<int MODE>
__global__ __launch_bounds__(THREADS, 1) void fused_level(
    const float* __restrict__ x0,
    const __half* __restrict__ Hprev, const int* __restrict__ idx,
    const float* __restrict__ b2, const float* __restrict__ xl,
    float* __restrict__ yout,
    const __half* __restrict__ W1h, const float* __restrict__ b1,
    const __half* __restrict__ W2h, __half* __restrict__ Hout)
{
    extern __shared__ __half smh[];
    const uint32_t smb = smem_u32(smh);

    const int tid = threadIdx.x;
    const int lane = tid & 31, wid = tid >> 5;
    const int g = lane >> 2, t = lane & 3;
    const int wm = (wid & 3) * 32;           // 4 m-warps
    const int wn = (wid >> 2) * 64;          // 4 n-warps
    const int bm = blockIdx.x * BM;

    // ---- B (weights) cp.async mapping: 256 rows x 8x16B, 4 rows/thread ----
    const int ar0 = tid >> 3, av0 = tid & 7;            // ar0 in [0,64)
    auto issueBchunk = [&](int chunk) {                 // chunk 0-3: W1, 4-7: W2
        const int stage = chunk % BSTAGES;
        const __half* W = (chunk < 4) ? W1h : W2h;
        const __half* src = W + (size_t)ar0 * DD + (chunk & 3) * BK + av0 * 8;
        const uint32_t dst = smb + (uint32_t)(BOFF + stage * BCH + ar0 * PADH + av0 * 8) * 2u;
        #pragma unroll
        for (int i = 0; i < 4; i++)
            cp16(dst + (uint32_t)(i * 64 * PADH) * 2u, src + (size_t)(i * 64) * DD);
        CP_COMMIT();
    };

    // Kick W1 chunks 0,1 so they land while the prologue gathers.
    issueBchunk(0);
    issueBchunk(1);

    // ================= Prologue: build A (fp16) in MSG buffers =================
    if (MODE == 0) {
        // convert x0 rows [bm, bm+128) to fp16 operand layout
        #pragma unroll
        for (int pass = 0; pass < 4; pass++) {
            const int e = tid + pass * 512;             // 0..2047
            const int r = e >> 4, co = (e & 15) * 16;   // 16 cols per element
            const float4* xs = (const float4*)(x0 + (size_t)(bm + r) * DD + co);
            uint4 hv[2];
            #pragma unroll
            for (int h = 0; h < 2; h++) {
                float4 v0 = xs[h * 2], v1 = xs[h * 2 + 1];
                __half2* hq = (__half2*)&hv[h];
                hq[0] = __float22half2_rn(make_float2(v0.x, v0.y));
                hq[1] = __float22half2_rn(make_float2(v0.z, v0.w));
                hq[2] = __float22half2_rn(make_float2(v1.x, v1.y));
                hq[3] = __float22half2_rn(make_float2(v1.z, v1.w));
            }
            const int ch = co >> 6, kcol = co & 63;
            *(uint4*)(smh + ch * ACH + r * PADH + kcol) = hv[0];
            *(uint4*)(smh + ch * ACH + r * PADH + kcol + 8) = hv[1];
        }
    } else {
        // gather: y = relu(mean_p Hprev[idx_p] + b2) + xl ; write yout ; A = fp16(y)
        #pragma unroll
        for (int pass = 0; pass < 8; pass++) {
            const int r = pass * 16 + (tid >> 5);       // 0..127
            const int node = bm + r;
            const int co = lane * 8;
            const int4* ip = (const int4*)(idx + (size_t)node * KP);
            int pr[KP];
            #pragma unroll
            for (int i = 0; i < 4; i++) {
                int4 v = ip[i];
                pr[i*4+0] = v.x; pr[i*4+1] = v.y; pr[i*4+2] = v.z; pr[i*4+3] = v.w;
            }
            float s[8] = {};
            #pragma unroll
            for (int p = 0; p < KP; p++) {
                uint4 u = *(const uint4*)(Hprev + (size_t)pr[p] * DD + co);
                const __half2* hp = (const __half2*)&u;
                #pragma unroll
                for (int j = 0; j < 4; j++) {
                    float2 f = __half22float2(hp[j]);
                    s[j*2]   += f.x;
                    s[j*2+1] += f.y;
                }
            }
            const float inv = 1.0f / (float)KP;
            float4 bb0 = *(const float4*)(b2 + co);
            float4 bb1 = *(const float4*)(b2 + co + 4);
            float4 xx0 = *(const float4*)(xl + (size_t)node * DD + co);
            float4 xx1 = *(const float4*)(xl + (size_t)node * DD + co + 4);
            float o[8];
            o[0] = fmaxf(s[0]*inv + bb0.x, 0.f) + xx0.x;
            o[1] = fmaxf(s[1]*inv + bb0.y, 0.f) + xx0.y;
            o[2] = fmaxf(s[2]*inv + bb0.z, 0.f) + xx0.z;
            o[3] = fmaxf(s[3]*inv + bb0.w, 0.f) + xx0.w;
            o[4] = fmaxf(s[4]*inv + bb1.x, 0.f) + xx1.x;
            o[5] = fmaxf(s[5]*inv + bb1.y, 0.f) + xx1.y;
            o[6] = fmaxf(s[6]*inv + bb1.z, 0.f) + xx1.z;
            o[7] = fmaxf(s[7]*inv + bb1.w, 0.f) + xx1.w;
            float4* yo = (float4*)(yout + (size_t)node * DD + co);
            yo[0] = make_float4(o[0], o[1], o[2], o[3]);
            yo[1] = make_float4(o[4], o[5], o[6], o[7]);
            uint4 hv;
            __half2* hq = (__half2*)&hv;
            hq[0] = __float22half2_rn(make_float2(o[0], o[1]));
            hq[1] = __float22half2_rn(make_float2(o[2], o[3]));
            hq[2] = __float22half2_rn(make_float2(o[4], o[5]));
            hq[3] = __float22half2_rn(make_float2(o[6], o[7]));
            const int ch = co >> 6, kcol = co & 63;
            *(uint4*)(smh + ch * ACH + r * PADH + kcol) = hv;
        }
    }

    // ---- ldmatrix lane mappings ----
    const int arow = lane & 15;
    const int acol = (lane >> 4) * 8;
    const int brow = (lane & 7) + ((lane >> 4) << 3);
    const int bcol = ((lane >> 3) & 1) * 8;
    uint32_t a_off[2], b_off[4];
    #pragma unroll
    for (int mf = 0; mf < 2; mf++)
        a_off[mf] = (uint32_t)((wm + mf * 16 + arow) * PADH + acol) * 2u;
    #pragma unroll
    for (int np = 0; np < 4; np++)
        b_off[np] = (uint32_t)(BOFF + (wn + np * 16 + brow) * PADH + bcol) * 2u;

    float acc[2][8][4] = {};

    auto compute = [&](int akc, int stage) {
        const uint32_t abase = smb + (uint32_t)(akc * ACH) * 2u;
        const uint32_t bbase = smb + (uint32_t)(stage * BCH) * 2u;
        #pragma unroll
        for (int ks = 0; ks < 4; ks++) {
            const uint32_t ko = ks * 32u;
            uint32_t a[2][4], b[4][4];
            #pragma unroll
            for (int mf = 0; mf < 2; mf++)
                ldsm4(a[mf][0], a[mf][1], a[mf][2], a[mf][3], abase + a_off[mf] + ko);
            #pragma unroll
            for (int np = 0; np < 4; np++)
                ldsm4(b[np][0], b[np][1], b[np][2], b[np][3], bbase + b_off[np] + ko);
            #pragma unroll
            for (int mf = 0; mf < 2; mf++)
                #pragma unroll
                for (int nf = 0; nf < 8; nf++)
                    mma_f16(acc[mf][nf],
                            a[mf][0], a[mf][1], a[mf][2], a[mf][3],
                            b[nf >> 1][(nf & 1) * 2], b[nf >> 1][(nf & 1) * 2 + 1]);
        }
    };

    // ================= Phase 1: MSG = relu(A @ W1 + b1) =================
    // Single sync per chunk (3-stage B ring; issue chunk k+2 after the sync).
    #pragma unroll
    for (int kc = 0; kc < NCH; kc++) {
        CP_WAIT(1);
        __syncthreads();
        issueBchunk(kc + 2);                 // chunks 2,3 (W1) then 4,5 (W2)
        compute(kc, kc % BSTAGES);
    }
    __syncthreads();                         // all A-reads done before MSG overwrite

    // Phase-1 epilogue: relu(acc + b1) -> MSG buffers as fp16 (A-operand layout)
    #pragma unroll
    for (int mf = 0; mf < 2; mf++) {
        const int r0 = wm + mf * 16 + g;
        #pragma unroll
        for (int nf = 0; nf < 8; nf++) {
            const int col = wn + nf * 8 + 2 * t;
            const int ch = col >> 6, kcol = col & 63;
            float2 bb = *(const float2*)(b1 + col);
            float2 v0, v1;
            v0.x = fmaxf(acc[mf][nf][0] + bb.x, 0.f);
            v0.y = fmaxf(acc[mf][nf][1] + bb.y, 0.f);
            v1.x = fmaxf(acc[mf][nf][2] + bb.x, 0.f);
            v1.y = fmaxf(acc[mf][nf][3] + bb.y, 0.f);
            *(__half2*)(smh + ch * ACH + r0 * PADH + kcol) = __float22half2_rn(v0);
            *(__half2*)(smh + ch * ACH + (r0 + 8) * PADH + kcol) = __float22half2_rn(v1);
            acc[mf][nf][0] = 0.f; acc[mf][nf][1] = 0.f;
            acc[mf][nf][2] = 0.f; acc[mf][nf][3] = 0.f;
        }
    }

    // ================= Phase 2: H = MSG @ W2 =================
    #pragma unroll
    for (int kc = 0; kc < NCH; kc++) {
        if (kc < 3) { CP_WAIT(1); } else { CP_WAIT(0); }
        __syncthreads();                     // publishes MSG writes (kc==0); stage ready
        if (kc < 2) issueBchunk(kc + 6);     // chunks 6,7 (W2)
        compute(kc, (kc + 4) % BSTAGES);
    }

    // Phase-2 epilogue: H to GMEM as fp16
    #pragma unroll
    for (int mf = 0; mf < 2; mf++) {
        const int r0 = bm + wm + mf * 16 + g;
        #pragma unroll
        for (int nf = 0; nf < 8; nf++) {
            const int col = wn + nf * 8 + 2 * t;
            float2 v0, v1;
            v0.x = acc[mf][nf][0]; v0.y = acc[mf][nf][1];
            v1.x = acc[mf][nf][2]; v1.y = acc[mf][nf][3];
            *(__half2*)(Hout + (size_t)r0 * DD + col) = __float22half2_rn(v0);
            *(__half2*)(Hout + (size_t)(r0 + 8) * DD + col) = __float22half2_rn(v1);
        }
    }
}

// ------- Final gather: y = relu(mean_p H[idx_p] + b2) + x -------
__global__ __launch_bounds__(256) void gather_epi(
    const __half* __restrict__ H, const int* __restrict__ idx,
    const float* __restrict__ b2, const float* __restrict__ x,
    float* __restrict__ y)
{
    const int node = blockIdx.x * 8 + (threadIdx.x >> 5);
    const int co = (threadIdx.x & 31) * 8;
    const int4* ip = (const int4*)(idx + (size_t)node * KP);

    int pr[KP];
    #pragma unroll
    for (int i = 0; i < 4; i++) {
        int4 v = ip[i];
        pr[i*4+0] = v.x; pr[i*4+1] = v.y; pr[i*4+2] = v.z; pr[i*4+3] = v.w;
    }
    float s[8] = {};
    #pragma unroll
    for (int p = 0; p < KP; p++) {
        uint4 u = *(const uint4*)(H + (size_t)pr[p] * DD + co);
        const __half2* hp = (const __half2*)&u;
        #pragma unroll
        for (int j = 0; j < 4; j++) {
            float2 f = __half22float2(hp[j]);
            s[j*2]   += f.x;
            s[j*2+1] += f.y;
        }
    }
    const float inv = 1.0f / (float)KP;
    float4 bb0 = *(const float4*)(b2 + co);
    float4 bb1 = *(const float4*)(b2 + co + 4);
    float4 xx0 = *(const float4*)(x + (size_t)node * DD + co);
    float4 xx1 = *(const float4*)(x + (size_t)node * DD + co + 4);
    float4* yo = (float4*)(y + (size_t)node * DD + co);
    yo[0] = make_float4(fmaxf(s[0]*inv + bb0.x, 0.f) + xx0.x,
                        fmaxf(s[1]*inv + bb0.y, 0.f) + xx0.y,
                        fmaxf(s[2]*inv + bb0.z, 0.f) + xx0.z,
                        fmaxf(s[3]*inv + bb0.w, 0.f) + xx0.w);
    yo[1] = make_float4(fmaxf(s[4]*inv + bb1.x, 0.f) + xx1.x,
                        fmaxf(s[5]*inv + bb1.y, 0.f) + xx1.y,
                        fmaxf(s[6]*inv + bb1.z, 0.f) + xx1.z,
                        fmaxf(s[7]*inv + bb1.w, 0.f) + xx1.w);
}

// ------- 256x256 transpose + fp16 rna (weights -> N-major fp16 B operand) -------
__global__ void transpose256h(const float* __restrict__ W, __half* __restrict__ Wt) {
    __shared__ float tbuf[32][33];
    const int bx = (blockIdx.x & 7) * 32;
    const int by = (blockIdx.x >> 3) * 32;
    const int x = threadIdx.x, y = threadIdx.y;
    #pragma unroll
    for (int i = 0; i < 32; i += 8)
        tbuf[y + i][x] = W[(by + y + i) * DD + bx + x];
    __syncthreads();
    #pragma unroll
    for (int i = 0; i < 32; i += 8)
        Wt[(bx + y + i) * DD + by + x] = __float2half_rn(tbuf[x][y + i]);
}

// ---------------- Launch ----------------
extern "C" void kernel_launch(void* const* d_in, const int* in_sizes, int n_in,
                              void* d_out, int out_size)
{
    const float* x   = (const float*)d_in[0];   // [L, N, D]
    const int*   idx = (const int*)  d_in[1];   // [L-1, N, K]
    const float* W1  = (const float*)d_in[2];   // [D, D]
    const float* b1  = (const float*)d_in[3];   // [D]
    const float* W2  = (const float*)d_in[4];   // [D, D]
    const float* b2  = (const float*)d_in[5];   // [D]
    float* out = (float*)d_out;                 // [L, N, D]

    __half *Ha, *Hb, *w1h, *w2h;
    cudaGetSymbolAddress((void**)&Ha,  g_Ha);
    cudaGetSymbolAddress((void**)&Hb,  g_Hb);
    cudaGetSymbolAddress((void**)&w1h, g_W1h);
    cudaGetSymbolAddress((void**)&w2h, g_W2h);

    cudaFuncSetAttribute(fused_level<0>, cudaFuncAttributeMaxDynamicSharedMemorySize, SMEM_BYTES);
    cudaFuncSetAttribute(fused_level<1>, cudaFuncAttributeMaxDynamicSharedMemorySize, SMEM_BYTES);

    const size_t lvl = (size_t)NN * DD;

    transpose256h<<<64, dim3(32, 8)>>>(W1, w1h);
    transpose256h<<<64, dim3(32, 8)>>>(W2, w2h);

    // Level 0: fp32 passthrough
    cudaMemcpyAsync(out, x, lvl * sizeof(float), cudaMemcpyDeviceToDevice);

    const int grid = NN / BM;   // 128 CTAs

    __half* Hbuf[2] = {Ha, Hb};

    // H_1 = relu(x0 @ W1 + b1) @ W2
    fused_level<0><<<grid, THREADS, SMEM_BYTES>>>(
        x, nullptr, nullptr, nullptr, nullptr, nullptr, w1h, b1, w2h, Hbuf[0]);

    // Levels 1..14: gather prologue (y_l) + GEMMs (H_{l+1})
    for (int l = 1; l <= 14; l++) {
        fused_level<1><<<grid, THREADS, SMEM_BYTES>>>(
            nullptr, Hbuf[(l - 1) & 1], idx + (size_t)(l - 1) * NN * KP,
            b2, x + (size_t)l * lvl, out + (size_t)l * lvl,
            w1h, b1, w2h, Hbuf[l & 1]);
    }

    // Level 15: final gather
    gather_epi<<<NN / 8, 256>>>(Hbuf[14 & 1], idx + (size_t)14 * NN * KP, b2,
                                x + (size_t)15 * lvl, out + (size_t)15 * lvl);
}